// round 12
// baseline (speedup 1.0000x reference)
#include <cuda_runtime.h>

// ChronoRotationTransflormation: per-row normalized complex inner product.
// Inputs: head_real, head_imag, rel_real, rel_imag, tail_real, tail_imag
// all float32 [8192, 2048]. Output: float32 [8192].
//
// R10: 2 rows per 1024-thread CTA. Per-thread work identical to R9
// (one float4 per array, 6 front-batched streaming LDG.128, ~32 regs),
// but half the CTAs -> half the reduction/barrier tails per byte streamed.
// Threads 0-511 handle row 2b, threads 512-1023 handle row 2b+1.

#define D 2048
#define DV (D / 4)              // 512 float4 per row
#define THREADS 1024
#define ROWS_PER_CTA 2
#define WARPS_PER_ROW 16        // 512 threads per row

__global__ __launch_bounds__(THREADS)
void chrono_rot_kernel(const float4* __restrict__ hr,
                       const float4* __restrict__ hi,
                       const float4* __restrict__ rr,
                       const float4* __restrict__ ri,
                       const float4* __restrict__ tr,
                       const float4* __restrict__ ti,
                       float* __restrict__ out)
{
    // Thread t covers element (t % 512) of row (2*blockIdx + t/512).
    // Global float4 index is simply blockIdx*1024 + t because rows are
    // contiguous: row*512 + elem = (2b + t/512)*512 + (t%512) = b*1024 + t.
    const long long idx = (long long)blockIdx.x * (DV * ROWS_PER_CTA) + threadIdx.x;

    const float4 HR = __ldcs(hr + idx);
    const float4 HI = __ldcs(hi + idx);
    const float4 RR = __ldcs(rr + idx);
    const float4 RI = __ldcs(ri + idx);
    const float4 TR = __ldcs(tr + idx);
    const float4 TI = __ldcs(ti + idx);

    float ab = 0.f, aa = 0.f, bb = 0.f;
    #pragma unroll
    for (int k = 0; k < 4; ++k) {
        const float h_r = (&HR.x)[k], h_i = (&HI.x)[k];
        const float r_r = (&RR.x)[k], r_i = (&RI.x)[k];
        const float t_r = (&TR.x)[k], t_i = (&TI.x)[k];
        const float rot_r = h_r * r_r - h_i * r_i;
        const float rot_i = -(h_i * r_r + h_r * r_i);
        ab = fmaf(rot_r, t_r, fmaf(rot_i, t_i, ab));
        aa = fmaf(rot_r, rot_r, fmaf(rot_i, rot_i, aa));
        bb = fmaf(t_r, t_r, fmaf(t_i, t_i, bb));
    }

    // Warp butterfly reduction.
    #pragma unroll
    for (int off = 16; off > 0; off >>= 1) {
        ab += __shfl_xor_sync(0xFFFFFFFFu, ab, off);
        aa += __shfl_xor_sync(0xFFFFFFFFu, aa, off);
        bb += __shfl_xor_sync(0xFFFFFFFFu, bb, off);
    }

    __shared__ float s_ab[32], s_aa[32], s_bb[32];   // 16 warps per row x 2 rows
    const int wid = threadIdx.x >> 5;                // 0..31
    const int lid = threadIdx.x & 31;
    if (lid == 0) {
        s_ab[wid] = ab;
        s_aa[wid] = aa;
        s_bb[wid] = bb;
    }
    __syncthreads();

    // Row 0 finalized by warp 0 (partials in s_*[0..15]);
    // row 1 finalized by warp 16 (partials in s_*[16..31]).
    if (wid == 0 || wid == WARPS_PER_ROW) {
        const int base = wid;                        // 0 or 16
        float tab = (lid < WARPS_PER_ROW) ? s_ab[base + lid] : 0.f;
        float taa = (lid < WARPS_PER_ROW) ? s_aa[base + lid] : 0.f;
        float tbb = (lid < WARPS_PER_ROW) ? s_bb[base + lid] : 0.f;
        #pragma unroll
        for (int off = 8; off > 0; off >>= 1) {
            tab += __shfl_xor_sync(0xFFFFFFFFu, tab, off);
            taa += __shfl_xor_sync(0xFFFFFFFFu, taa, off);
            tbb += __shfl_xor_sync(0xFFFFFFFFu, tbb, off);
        }
        if (lid == 0)
            out[blockIdx.x * ROWS_PER_CTA + (wid >> 4)] = tab / sqrtf(taa * tbb);
    }
}

extern "C" void kernel_launch(void* const* d_in, const int* in_sizes, int n_in,
                              void* d_out, int out_size)
{
    const float4* hr = (const float4*)d_in[0];
    const float4* hi = (const float4*)d_in[1];
    const float4* rr = (const float4*)d_in[2];
    const float4* ri = (const float4*)d_in[3];
    const float4* tr = (const float4*)d_in[4];
    const float4* ti = (const float4*)d_in[5];
    float* out = (float*)d_out;

    const int rows = out_size;  // 8192
    chrono_rot_kernel<<<rows / ROWS_PER_CTA, THREADS>>>(hr, hi, rr, ri, tr, ti, out);
}